// round 11
// baseline (speedup 1.0000x reference)
#include <cuda_runtime.h>
#include <math.h>

#define BATCH 8
#define HW    4096
#define CH    2048
#define NBC   (BATCH*CH)
#define NSEL  (CH*3)

__device__ float g_stats[NBC * 3];
__device__ float g_gate[NBC];
__device__ int   g_cnt[BATCH];      // zero at load; K3 re-zeros each run

// ---- 256-bit loads (sm_103a: evict hints require v8) ----------------------
struct F8 { float v[8]; };
__device__ __forceinline__ F8 ldg256_ef(const float* p) {
    unsigned u0,u1,u2,u3,u4,u5,u6,u7;
    asm("ld.global.L2::evict_first.v8.b32 {%0,%1,%2,%3,%4,%5,%6,%7}, [%8];"
        : "=r"(u0),"=r"(u1),"=r"(u2),"=r"(u3),
          "=r"(u4),"=r"(u5),"=r"(u6),"=r"(u7) : "l"(p));
    F8 r;
    r.v[0]=__uint_as_float(u0); r.v[1]=__uint_as_float(u1);
    r.v[2]=__uint_as_float(u2); r.v[3]=__uint_as_float(u3);
    r.v[4]=__uint_as_float(u4); r.v[5]=__uint_as_float(u5);
    r.v[6]=__uint_as_float(u6); r.v[7]=__uint_as_float(u7);
    return r;
}

__device__ __forceinline__ unsigned f2k(float f) {
    unsigned u = __float_as_uint(f);
    return (u & 0x80000000u) ? ~u : (u | 0x80000000u);
}
__device__ __forceinline__ float k2f(unsigned k) {
    unsigned u = (k & 0x80000000u) ? (k ^ 0x80000000u) : ~k;
    return __uint_as_float(u);
}

// ---------------------------------------------------------------------------
// K1: blocks 0..7 = median spinners (one per batch); blocks 8..16391 = stats.
// Stats stream in reverse bc order (batch 7 first), so batch b's counter hits
// CH at ~(8-b)/8 of the kernel; spinner b then runs median+gate while the
// remaining batches keep streaming. Only the last batch's median is exposed.
// ---------------------------------------------------------------------------
__global__ __launch_bounds__(256) void k_stats_med(const float* __restrict__ x,
                                                   const float* __restrict__ cfc_w,
                                                   const float* __restrict__ bn_w,
                                                   const float* __restrict__ bn_b) {
    __shared__ unsigned hist[8][256];        // 8 KB (spinners; harmless for stats blocks)
    __shared__ unsigned s_prefix;
    __shared__ int      s_rank;
    __shared__ unsigned s_eq;
    __shared__ unsigned s_wmin[8];

    int tid = threadIdx.x;

    if (blockIdx.x >= BATCH) {
        // ---------------- stats block ----------------
        int bc = NBC - 1 - (int)(blockIdx.x - BATCH);
        int b  = bc >> 11;                   // bc / CH
        const float* p = x + (size_t)bc * HW;

        float s = 0.f, s2 = 0.f, mx = -INFINITY;
        F8 d[2];
#pragma unroll
        for (int i = 0; i < 2; i++)
            d[i] = ldg256_ef(p + (tid + i * 256) * 8);
#pragma unroll
        for (int i = 0; i < 2; i++)
#pragma unroll
            for (int j = 0; j < 8; j++) {
                float f = d[i].v[j];
                s += f; s2 += f * f; mx = fmaxf(mx, f);
            }
#pragma unroll
        for (int o = 16; o; o >>= 1) {
            s  += __shfl_xor_sync(0xffffffffu, s, o);
            s2 += __shfl_xor_sync(0xffffffffu, s2, o);
            mx = fmaxf(mx, __shfl_xor_sync(0xffffffffu, mx, o));
        }
        __shared__ float ss[8], ss2[8], sm[8];
        int w = tid >> 5;
        if ((tid & 31) == 0) { ss[w] = s; ss2[w] = s2; sm[w] = mx; }
        __syncthreads();
        if (tid == 0) {
            s = ss[0]; s2 = ss2[0]; mx = sm[0];
#pragma unroll
            for (int i = 1; i < 8; i++) { s += ss[i]; s2 += ss2[i]; mx = fmaxf(mx, sm[i]); }
            float mean = s / (float)HW;
            float var  = (s2 - (float)HW * mean * mean) / (float)(HW - 1);
            var = fmaxf(var, 0.f);
            float* o = g_stats + (size_t)bc * 3;
            o[0] = mean;
            o[1] = mx;
            o[2] = sqrtf(var);
            __threadfence();                 // publish stats before counting
            atomicAdd(&g_cnt[b], 1);
        }
        return;
    }

    // ---------------- spinner block: median + gate for batch b ----------------
    int b = blockIdx.x;
    int lane = tid & 31, warp = tid >> 5;
    const float* st = g_stats + (size_t)b * NSEL;

    if (tid == 0) {
        while (atomicAdd(&g_cnt[b], 0) < CH) { __nanosleep(256); }
    }
    __syncthreads();
    __threadfence();                         // acquire

    int rank = NSEL / 2 - 1;                 // 3071
    unsigned prefix = 0;
    for (int shift = 24; shift >= 0; shift -= 8) {
#pragma unroll
        for (int i = tid; i < 8 * 256; i += 256) (&hist[0][0])[i] = 0u;
        __syncthreads();
        unsigned mhi = (shift == 24) ? 0u : (0xFFFFFFFFu << (shift + 8));
        for (int i = tid; i < NSEL; i += 256) {
            unsigned k = f2k(st[i]);
            if ((k & mhi) == prefix)
                atomicAdd(&hist[warp][(k >> shift) & 255u], 1u);
        }
        __syncthreads();
        {
            unsigned a = 0;
#pragma unroll
            for (int j = 0; j < 8; j++) a += hist[j][tid];
            __syncthreads();
            hist[0][tid] = a;
        }
        __syncthreads();
        if (warp == 0) {
            unsigned part = 0;
#pragma unroll
            for (int j = 0; j < 8; j++) part += hist[0][lane * 8 + j];
            unsigned p = part;
#pragma unroll
            for (int o = 1; o < 32; o <<= 1) {
                unsigned t = __shfl_up_sync(0xffffffffu, p, o);
                if (lane >= o) p += t;
            }
            unsigned excl = p - part;
            unsigned mask = __ballot_sync(0xffffffffu, (int)excl <= rank);
            int lead = 31 - __clz(mask);
            if (lane == lead) {
                int r = rank - (int)excl;
                int d = lane * 8;
                unsigned cnt = 0;
#pragma unroll
                for (int j = 0; j < 8; j++) {
                    cnt = hist[0][lane * 8 + j];
                    if (r < (int)cnt) { d = lane * 8 + j; break; }
                    r -= (int)cnt;
                }
                s_prefix = prefix | ((unsigned)d << shift);
                s_rank   = r;
                s_eq     = cnt;
            }
        }
        __syncthreads();
        prefix = s_prefix;
        rank   = s_rank;
    }

    unsigned k0 = prefix;
    float v0 = k2f(k0), v1;
    if ((unsigned)(rank + 1) < s_eq) {
        v1 = v0;
    } else {
        unsigned m = 0xFFFFFFFFu;
        for (int i = tid; i < NSEL; i += 256) {
            unsigned k = f2k(st[i]);
            if (k > k0) m = min(m, k);
        }
#pragma unroll
        for (int o = 16; o; o >>= 1) m = min(m, __shfl_xor_sync(0xffffffffu, m, o));
        if (lane == 0) s_wmin[warp] = m;
        __syncthreads();
        if (tid == 0) {
            unsigned mm = s_wmin[0];
#pragma unroll
            for (int j = 1; j < 8; j++) mm = min(mm, s_wmin[j]);
            s_prefix = mm;
        }
        __syncthreads();
        v1 = k2f(s_prefix);
    }
    float med = 0.5f * (v0 + v1);

    const float inv = rsqrtf(1.0f + 1e-5f);
    for (int c = tid; c < CH; c += 256) {
        float u0 = st[c * 3 + 0] - med;
        float u1 = st[c * 3 + 1] - med;
        float u2 = st[c * 3 + 2] - med;
        float z = (u0 * u0 * u0) * cfc_w[c * 3 + 0]
                + (u1 * u1 * u1) * cfc_w[c * 3 + 1]
                + (u2 * u2 * u2) * cfc_w[c * 3 + 2];
        z = z * inv * bn_w[c] + bn_b[c];
        g_gate[b * CH + c] = 1.f / (1.f + expf(-z));
    }
}

// ---------------------------------------------------------------------------
// K3: pure scale (proven R7 body). 2 ch/block, 8 front-batched __ldcs float4
// loads, 8 __stcs stores. Block 0 resets counters for the next graph replay.
// ---------------------------------------------------------------------------
__global__ __launch_bounds__(256) void k_scale(const float* __restrict__ x,
                                               float* __restrict__ out) {
    if (blockIdx.x == 0 && threadIdx.x < BATCH) g_cnt[threadIdx.x] = 0;

    int c0 = (int)blockIdx.x * 2;
    size_t base = (size_t)c0 * (HW / 4);
    const float4* px = reinterpret_cast<const float4*>(x) + base;
    float4*       po = reinterpret_cast<float4*>(out)     + base;
    float g0 = g_gate[c0];
    float g1 = g_gate[c0 + 1];

    float4 v[8];
#pragma unroll
    for (int i = 0; i < 8; i++)
        v[i] = __ldcs(px + threadIdx.x + i * 256);
#pragma unroll
    for (int i = 0; i < 8; i++) {
        float g = (i < 4) ? g0 : g1;
        v[i].x *= g; v[i].y *= g; v[i].z *= g; v[i].w *= g;
        __stcs(po + threadIdx.x + i * 256, v[i]);
    }
}

extern "C" void kernel_launch(void* const* d_in, const int* in_sizes, int n_in,
                              void* d_out, int out_size) {
    const float* x     = (const float*)d_in[0];
    const float* cfc_w = (const float*)d_in[1];
    const float* bn_w  = (const float*)d_in[2];
    const float* bn_b  = (const float*)d_in[3];
    float* out = (float*)d_out;

    k_stats_med<<<BATCH + NBC, 256>>>(x, cfc_w, bn_w, bn_b);
    k_scale<<<NBC / 2, 256>>>(x, out);
}

// round 13
// speedup vs baseline: 1.0161x; 1.0161x over previous
#include <cuda_runtime.h>
#include <math.h>

#define BATCH 8
#define HW    4096
#define CH    2048
#define NBC   (BATCH*CH)
#define NSEL  (CH*3)

__device__ float g_stats[NBC * 3];
__device__ float g_gate[NBC];

// ---- 256-bit load, evict_first (sm_103a requires v8 for L2 hints) ---------
struct F8 { float v[8]; };
__device__ __forceinline__ F8 ldg256_ef(const float* p) {
    unsigned u0,u1,u2,u3,u4,u5,u6,u7;
    asm("ld.global.L2::evict_first.v8.b32 {%0,%1,%2,%3,%4,%5,%6,%7}, [%8];"
        : "=r"(u0),"=r"(u1),"=r"(u2),"=r"(u3),
          "=r"(u4),"=r"(u5),"=r"(u6),"=r"(u7) : "l"(p));
    F8 r;
    r.v[0]=__uint_as_float(u0); r.v[1]=__uint_as_float(u1);
    r.v[2]=__uint_as_float(u2); r.v[3]=__uint_as_float(u3);
    r.v[4]=__uint_as_float(u4); r.v[5]=__uint_as_float(u5);
    r.v[6]=__uint_as_float(u6); r.v[7]=__uint_as_float(u7);
    return r;
}

// ---------------------------------------------------------------------------
// K1: per-(b,c) stats, reverse block order, 2x LDG.256 per thread.
// (R9 body — measured 40.9us, 83.4% DRAM.)
// ---------------------------------------------------------------------------
__global__ __launch_bounds__(256) void k_stats(const float* __restrict__ x) {
    int bc = NBC - 1 - blockIdx.x;
    const float* p = x + (size_t)bc * HW;

    float s = 0.f, s2 = 0.f, mx = -INFINITY;
    F8 d[2];
#pragma unroll
    for (int i = 0; i < 2; i++)
        d[i] = ldg256_ef(p + (threadIdx.x + i * 256) * 8);
#pragma unroll
    for (int i = 0; i < 2; i++)
#pragma unroll
        for (int j = 0; j < 8; j++) {
            float f = d[i].v[j];
            s += f; s2 += f * f; mx = fmaxf(mx, f);
        }
#pragma unroll
    for (int o = 16; o; o >>= 1) {
        s  += __shfl_xor_sync(0xffffffffu, s, o);
        s2 += __shfl_xor_sync(0xffffffffu, s2, o);
        mx = fmaxf(mx, __shfl_xor_sync(0xffffffffu, mx, o));
    }
    __shared__ float ss[8], ss2[8], sm[8];
    int w = threadIdx.x >> 5;
    if ((threadIdx.x & 31) == 0) { ss[w] = s; ss2[w] = s2; sm[w] = mx; }
    __syncthreads();
    if (threadIdx.x == 0) {
        s = ss[0]; s2 = ss2[0]; mx = sm[0];
#pragma unroll
        for (int i = 1; i < 8; i++) { s += ss[i]; s2 += ss2[i]; mx = fmaxf(mx, sm[i]); }
        float mean = s / (float)HW;
        float var  = (s2 - (float)HW * mean * mean) / (float)(HW - 1);
        var = fmaxf(var, 0.f);
        float* o = g_stats + (size_t)bc * 3;
        o[0] = mean;
        o[1] = mx;
        o[2] = sqrtf(var);
    }
}

// ---------------------------------------------------------------------------
// K2: per-batch exact median (avg of ranks 3071/3072) + gate.
// 8 blocks x 1024 threads (R3/R7 body — proven, ~4us).
// ---------------------------------------------------------------------------
__device__ __forceinline__ unsigned f2k(float f) {
    unsigned u = __float_as_uint(f);
    return (u & 0x80000000u) ? ~u : (u | 0x80000000u);
}
__device__ __forceinline__ float k2f(unsigned k) {
    unsigned u = (k & 0x80000000u) ? (k ^ 0x80000000u) : ~k;
    return __uint_as_float(u);
}

__global__ __launch_bounds__(1024) void k_median_gate(const float* __restrict__ cfc_w,
                                                      const float* __restrict__ bn_w,
                                                      const float* __restrict__ bn_b) {
    __shared__ unsigned keys[NSEL];
    __shared__ unsigned hist[16][256];
    __shared__ unsigned s_prefix;
    __shared__ int      s_rank;
    __shared__ unsigned s_eq;
    __shared__ unsigned s_wmin[32];

    int b = blockIdx.x, tid = threadIdx.x;
    int lane = tid & 31, warp = tid >> 5;
    const float* st = g_stats + (size_t)b * NSEL;

    for (int i = tid; i < NSEL; i += 1024) keys[i] = f2k(st[i]);
    __syncthreads();

    int rank = NSEL / 2 - 1;                 // 3071
    unsigned prefix = 0;
    for (int shift = 24; shift >= 0; shift -= 8) {
        for (int i = tid; i < 16 * 256; i += 1024) (&hist[0][0])[i] = 0u;
        __syncthreads();
        unsigned mhi = (shift == 24) ? 0u : (0xFFFFFFFFu << (shift + 8));
        int grp = tid >> 6;
        for (int i = tid; i < NSEL; i += 1024) {
            unsigned k = keys[i];
            if ((k & mhi) == prefix)
                atomicAdd(&hist[grp][(k >> shift) & 255u], 1u);
        }
        __syncthreads();
        if (tid < 256) {
            unsigned a = 0;
#pragma unroll
            for (int j = 0; j < 16; j++) a += hist[j][tid];
            hist[0][tid] = a;
        }
        __syncthreads();
        if (warp == 0) {
            unsigned part = 0;
#pragma unroll
            for (int j = 0; j < 8; j++) part += hist[0][lane * 8 + j];
            unsigned p = part;
#pragma unroll
            for (int o = 1; o < 32; o <<= 1) {
                unsigned t = __shfl_up_sync(0xffffffffu, p, o);
                if (lane >= o) p += t;
            }
            unsigned excl = p - part;
            unsigned mask = __ballot_sync(0xffffffffu, (int)excl <= rank);
            int lead = 31 - __clz(mask);
            if (lane == lead) {
                int r = rank - (int)excl;
                int d = lane * 8;
                unsigned cnt = 0;
#pragma unroll
                for (int j = 0; j < 8; j++) {
                    cnt = hist[0][lane * 8 + j];
                    if (r < (int)cnt) { d = lane * 8 + j; break; }
                    r -= (int)cnt;
                }
                s_prefix = prefix | ((unsigned)d << shift);
                s_rank   = r;
                s_eq     = cnt;
            }
        }
        __syncthreads();
        prefix = s_prefix;
        rank   = s_rank;
    }

    unsigned k0 = prefix;
    float v0 = k2f(k0), v1;
    if ((unsigned)(rank + 1) < s_eq) {
        v1 = v0;
    } else {
        unsigned m = 0xFFFFFFFFu;
        for (int i = tid; i < NSEL; i += 1024) {
            unsigned k = keys[i];
            if (k > k0) m = min(m, k);
        }
#pragma unroll
        for (int o = 16; o; o >>= 1) m = min(m, __shfl_xor_sync(0xffffffffu, m, o));
        if (lane == 0) s_wmin[warp] = m;
        __syncthreads();
        if (tid == 0) {
            unsigned mm = s_wmin[0];
#pragma unroll
            for (int j = 1; j < 32; j++) mm = min(mm, s_wmin[j]);
            s_prefix = mm;
        }
        __syncthreads();
        v1 = k2f(s_prefix);
    }
    float med = 0.5f * (v0 + v1);

    const float inv = rsqrtf(1.0f + 1e-5f);
    for (int c = tid; c < CH; c += 1024) {
        float u0 = st[c * 3 + 0] - med;
        float u1 = st[c * 3 + 1] - med;
        float u2 = st[c * 3 + 2] - med;
        float z = (u0 * u0 * u0) * cfc_w[c * 3 + 0]
                + (u1 * u1 * u1) * cfc_w[c * 3 + 1]
                + (u2 * u2 * u2) * cfc_w[c * 3 + 2];
        z = z * inv * bn_w[c] + bn_b[c];
        g_gate[b * CH + c] = 1.f / (1.f + expf(-z));
    }
}

// ---------------------------------------------------------------------------
// K3: out = x * g. 2 ch/block, 8 front-batched __ldcs float4 loads (MLP=8),
// then 8 __stcs stores. (R7 body — measured 75.7us standalone in R11.)
// ---------------------------------------------------------------------------
__global__ __launch_bounds__(256) void k_scale(const float* __restrict__ x,
                                               float* __restrict__ out) {
    int c0 = (int)blockIdx.x * 2;
    size_t base = (size_t)c0 * (HW / 4);
    const float4* px = reinterpret_cast<const float4*>(x) + base;
    float4*       po = reinterpret_cast<float4*>(out)     + base;
    float g0 = g_gate[c0];
    float g1 = g_gate[c0 + 1];

    float4 v[8];
#pragma unroll
    for (int i = 0; i < 8; i++)
        v[i] = __ldcs(px + threadIdx.x + i * 256);
#pragma unroll
    for (int i = 0; i < 8; i++) {
        float g = (i < 4) ? g0 : g1;
        v[i].x *= g; v[i].y *= g; v[i].z *= g; v[i].w *= g;
        __stcs(po + threadIdx.x + i * 256, v[i]);
    }
}

extern "C" void kernel_launch(void* const* d_in, const int* in_sizes, int n_in,
                              void* d_out, int out_size) {
    const float* x     = (const float*)d_in[0];
    const float* cfc_w = (const float*)d_in[1];
    const float* bn_w  = (const float*)d_in[2];
    const float* bn_b  = (const float*)d_in[3];
    float* out = (float*)d_out;

    k_stats<<<NBC, 256>>>(x);
    k_median_gate<<<BATCH, 1024>>>(cfc_w, bn_w, bn_b);
    k_scale<<<NBC / 2, 256>>>(x, out);
}

// round 17
// speedup vs baseline: 1.0209x; 1.0047x over previous
#include <cuda_runtime.h>
#include <math.h>

#define BATCH 8
#define HW    4096
#define CH    2048
#define NBC   (BATCH*CH)
#define NSEL  (CH*3)

__device__ float g_stats[NBC * 3];
__device__ float g_med[BATCH];

// ---- 256-bit load, evict_first (sm_103a requires v8 for L2 hints) ---------
struct F8 { float v[8]; };
__device__ __forceinline__ F8 ldg256_ef(const float* p) {
    unsigned u0,u1,u2,u3,u4,u5,u6,u7;
    asm("ld.global.L2::evict_first.v8.b32 {%0,%1,%2,%3,%4,%5,%6,%7}, [%8];"
        : "=r"(u0),"=r"(u1),"=r"(u2),"=r"(u3),
          "=r"(u4),"=r"(u5),"=r"(u6),"=r"(u7) : "l"(p));
    F8 r;
    r.v[0]=__uint_as_float(u0); r.v[1]=__uint_as_float(u1);
    r.v[2]=__uint_as_float(u2); r.v[3]=__uint_as_float(u3);
    r.v[4]=__uint_as_float(u4); r.v[5]=__uint_as_float(u5);
    r.v[6]=__uint_as_float(u6); r.v[7]=__uint_as_float(u7);
    return r;
}

// ---------------------------------------------------------------------------
// K1: per-(b,c) stats, reverse block order, 2x LDG.256 per thread.
// (Measured 40.6us, 84.6% DRAM — unchanged.)
// ---------------------------------------------------------------------------
__global__ __launch_bounds__(256) void k_stats(const float* __restrict__ x) {
    int bc = NBC - 1 - blockIdx.x;
    const float* p = x + (size_t)bc * HW;

    float s = 0.f, s2 = 0.f, mx = -INFINITY;
    F8 d[2];
#pragma unroll
    for (int i = 0; i < 2; i++)
        d[i] = ldg256_ef(p + (threadIdx.x + i * 256) * 8);
#pragma unroll
    for (int i = 0; i < 2; i++)
#pragma unroll
        for (int j = 0; j < 8; j++) {
            float f = d[i].v[j];
            s += f; s2 += f * f; mx = fmaxf(mx, f);
        }
#pragma unroll
    for (int o = 16; o; o >>= 1) {
        s  += __shfl_xor_sync(0xffffffffu, s, o);
        s2 += __shfl_xor_sync(0xffffffffu, s2, o);
        mx = fmaxf(mx, __shfl_xor_sync(0xffffffffu, mx, o));
    }
    __shared__ float ss[8], ss2[8], sm[8];
    int w = threadIdx.x >> 5;
    if ((threadIdx.x & 31) == 0) { ss[w] = s; ss2[w] = s2; sm[w] = mx; }
    __syncthreads();
    if (threadIdx.x == 0) {
        s = ss[0]; s2 = ss2[0]; mx = sm[0];
#pragma unroll
        for (int i = 1; i < 8; i++) { s += ss[i]; s2 += ss2[i]; mx = fmaxf(mx, sm[i]); }
        float mean = s / (float)HW;
        float var  = (s2 - (float)HW * mean * mean) / (float)(HW - 1);
        var = fmaxf(var, 0.f);
        float* o = g_stats + (size_t)bc * 3;
        o[0] = mean;
        o[1] = mx;
        o[2] = sqrtf(var);
    }
}

// ---------------------------------------------------------------------------
// K2: median ONLY (gate moved to K3). 3-pass radix select: 11/11/10 bits,
// 2048-bin histograms x 2 sub-copies. Avg of ranks 3071/3072.
// ---------------------------------------------------------------------------
__device__ __forceinline__ unsigned f2k(float f) {
    unsigned u = __float_as_uint(f);
    return (u & 0x80000000u) ? ~u : (u | 0x80000000u);
}
__device__ __forceinline__ float k2f(unsigned k) {
    unsigned u = (k & 0x80000000u) ? (k ^ 0x80000000u) : ~k;
    return __uint_as_float(u);
}

__global__ __launch_bounds__(1024) void k_median(const float* __restrict__ unused) {
    __shared__ unsigned keys[NSEL];          // 24 KB
    __shared__ unsigned hist[2][2048];       // 16 KB
    __shared__ unsigned s_prefix;
    __shared__ int      s_rank;
    __shared__ unsigned s_eq;
    __shared__ unsigned s_wmin[32];

    int b = blockIdx.x, tid = threadIdx.x;
    int lane = tid & 31, warp = tid >> 5;
    const float* st = g_stats + (size_t)b * NSEL;

    for (int i = tid; i < NSEL; i += 1024) keys[i] = f2k(st[i]);
    __syncthreads();

    const int shifts[3] = {21, 10, 0};
    const int nbinsv[3] = {2048, 2048, 1024};

    int rank = NSEL / 2 - 1;                 // 3071
    unsigned prefix = 0;
#pragma unroll
    for (int ps = 0; ps < 3; ps++) {
        int shift = shifts[ps];
        int nbins = nbinsv[ps];
        unsigned bmask = (unsigned)nbins - 1u;

        for (int i = tid; i < 2 * 2048; i += 1024) (&hist[0][0])[i] = 0u;
        __syncthreads();

        unsigned mhi = (ps == 0) ? 0u : (0xFFFFFFFFu << shifts[ps - 1]);
        int sub = tid >> 9;                  // 2 sub-histograms
        for (int i = tid; i < NSEL; i += 1024) {
            unsigned k = keys[i];
            if ((k & mhi) == prefix)
                atomicAdd(&hist[sub][(k >> shift) & bmask], 1u);
        }
        __syncthreads();
        for (int i = tid; i < nbins; i += 1024) hist[0][i] += hist[1][i];
        __syncthreads();

        if (warp == 0) {
            int per = nbins / 32;            // 64 or 32 bins per lane
            unsigned part = 0;
            for (int j = 0; j < per; j++) part += hist[0][lane * per + j];
            unsigned p = part;
#pragma unroll
            for (int o = 1; o < 32; o <<= 1) {
                unsigned t = __shfl_up_sync(0xffffffffu, p, o);
                if (lane >= o) p += t;
            }
            unsigned excl = p - part;
            unsigned mask = __ballot_sync(0xffffffffu, (int)excl <= rank);
            int lead = 31 - __clz(mask);
            if (lane == lead) {
                int r = rank - (int)excl;
                int d = lane * per;
                unsigned cnt = 0;
                for (int j = 0; j < per; j++) {
                    cnt = hist[0][lane * per + j];
                    if (r < (int)cnt) { d = lane * per + j; break; }
                    r -= (int)cnt;
                }
                s_prefix = prefix | ((unsigned)d << shift);
                s_rank   = r;
                s_eq     = cnt;              // meaningful on last pass
            }
        }
        __syncthreads();
        prefix = s_prefix;
        rank   = s_rank;
    }

    unsigned k0 = prefix;
    float v0 = k2f(k0), v1;
    if ((unsigned)(rank + 1) < s_eq) {
        v1 = v0;                             // rank 3072 same key
    } else {
        unsigned m = 0xFFFFFFFFu;
        for (int i = tid; i < NSEL; i += 1024) {
            unsigned k = keys[i];
            if (k > k0) m = min(m, k);
        }
#pragma unroll
        for (int o = 16; o; o >>= 1) m = min(m, __shfl_xor_sync(0xffffffffu, m, o));
        if (lane == 0) s_wmin[warp] = m;
        __syncthreads();
        if (tid == 0) {
            unsigned mm = s_wmin[0];
#pragma unroll
            for (int j = 1; j < 32; j++) mm = min(mm, s_wmin[j]);
            s_prefix = mm;
        }
        __syncthreads();
        v1 = k2f(s_prefix);
    }
    if (tid == 0) g_med[b] = 0.5f * (v0 + v1);
}

// ---------------------------------------------------------------------------
// K3: out = x * g. 2 ch/block; 8 front-batched __ldcs loads, then the gate
// math runs WHILE loads are in flight (hidden), then 8 __stcs stores.
// ---------------------------------------------------------------------------
__global__ __launch_bounds__(256) void k_scale(const float* __restrict__ x,
                                               float* __restrict__ out,
                                               const float* __restrict__ cfc_w,
                                               const float* __restrict__ bn_w,
                                               const float* __restrict__ bn_b) {
    int c0 = (int)blockIdx.x * 2;            // global channel pair (bc space)
    size_t base = (size_t)c0 * (HW / 4);
    const float4* px = reinterpret_cast<const float4*>(x) + base;
    float4*       po = reinterpret_cast<float4*>(out)     + base;

    float4 v[8];
#pragma unroll
    for (int i = 0; i < 8; i++)
        v[i] = __ldcs(px + threadIdx.x + i * 256);   // 8 outstanding loads

    // Gate math overlaps the load latency above.
    int b  = c0 >> 11;                       // bc / CH
    int ch = c0 & (CH - 1);                  // channel within batch
    float med = g_med[b];
    const float inv = rsqrtf(1.0f + 1e-5f);
    float g01[2];
#pragma unroll
    for (int j = 0; j < 2; j++) {
        const float* st = g_stats + ((size_t)c0 + j) * 3;
        int c = ch + j;
        float u0 = st[0] - med;
        float u1 = st[1] - med;
        float u2 = st[2] - med;
        float z = (u0 * u0 * u0) * cfc_w[c * 3 + 0]
                + (u1 * u1 * u1) * cfc_w[c * 3 + 1]
                + (u2 * u2 * u2) * cfc_w[c * 3 + 2];
        z = z * inv * bn_w[c] + bn_b[c];
        g01[j] = 1.f / (1.f + expf(-z));
    }

#pragma unroll
    for (int i = 0; i < 8; i++) {
        float g = (i < 4) ? g01[0] : g01[1];
        v[i].x *= g; v[i].y *= g; v[i].z *= g; v[i].w *= g;
        __stcs(po + threadIdx.x + i * 256, v[i]);
    }
}

extern "C" void kernel_launch(void* const* d_in, const int* in_sizes, int n_in,
                              void* d_out, int out_size) {
    const float* x     = (const float*)d_in[0];
    const float* cfc_w = (const float*)d_in[1];
    const float* bn_w  = (const float*)d_in[2];
    const float* bn_b  = (const float*)d_in[3];
    float* out = (float*)d_out;

    k_stats<<<NBC, 256>>>(x);
    k_median<<<BATCH, 1024>>>(x);
    k_scale<<<NBC / 2, 256>>>(x, out, cfc_w, bn_w, bn_b);
}